// round 9
// baseline (speedup 1.0000x reference)
#include <cuda_runtime.h>
#include <math.h>

// out[b,i,j] = pos_biases[j - i + n - 1]
//            + ts_w[ clamp( floor( log(clip(|f32(t[min(i+1,n-1)]) - f32(t[j])|, 1, 1e9)) / 0.301 ), 0, nb ) ]
//
// Log-free exact bucketing: cell = (float_bits(x) >> 20) - 1016 selects an
// exponent/top-3-mantissa cell of width ln2/8 = 0.288 buckets (< 1), so each
// cell holds at most ONE exact bucket boundary. s_tab[cell] = (thr, w_lo, w_hi);
// w = (x < thr) ? w_lo : w_hi. Thresholds thr[k] (smallest f32 with
// floor(fdiv_rn(log_rn(x),0.301f)) >= k) are ulp-exact, host-built.
// Bit-identical results to R3-R7 (rel_err 4.933e-4). Zero MUFU in hot loop.

struct CellTab {
    float thr[256];
    unsigned char klo[256];
    unsigned char khi[256];
};

__global__ void __launch_bounds__(256)
bias_kernel(const int*   __restrict__ ts,
            const float* __restrict__ pos,
            const float* __restrict__ tsw,
            float*       __restrict__ out,
            int n, int nb, CellTab tab) {
    extern __shared__ float sm[];
    float4* s_tab = (float4*)sm;              // 256 x (thr, w_lo, w_hi, 0) = 4KB
    float*  s_pos = sm + 1024;                // n + 16 floats

    const int b   = blockIdx.y;
    const int i0  = blockIdx.x * 8;
    const int tid = threadIdx.x;
    const int* trow = ts + (size_t)b * n;

    {   // table init: every thread owns one cell
        int c = tid;
        float wlo = tsw[min((int)tab.klo[c], nb)];
        float whi = tsw[min((int)tab.khi[c], nb)];
        s_tab[c] = make_float4(tab.thr[c], wlo, whi, 0.0f);
    }
    const int pbase = n - 8 - i0;
    for (int idx = tid; idx < n + 16; idx += 256) {
        int g = pbase + idx;
        s_pos[idx] = (g >= 0 && g <= 2 * n - 2) ? pos[g] : 0.0f;
    }
    __syncthreads();

    float tnr[8];
    #pragma unroll
    for (int r = 0; r < 8; ++r) tnr[r] = (float)__ldg(&trow[min(i0 + r + 1, n - 1)]);

    const bool full = (i0 + 8 <= n);
    float* oblk = out + ((size_t)b * n + i0) * (size_t)n;

    for (int jj = tid * 4; jj < n; jj += 1024) {
        int4 ti = *reinterpret_cast<const int4*>(trow + jj);
        const float tv0 = (float)ti.x, tv1 = (float)ti.y,
                    tv2 = (float)ti.z, tv3 = (float)ti.w;
        float4 p0 = *reinterpret_cast<const float4*>(s_pos + jj);
        float4 p1 = *reinterpret_cast<const float4*>(s_pos + jj + 4);
        float4 p2 = *reinterpret_cast<const float4*>(s_pos + jj + 8);
        const float pw[12] = {p0.x, p0.y, p0.z, p0.w,
                              p1.x, p1.y, p1.z, p1.w,
                              p2.x, p2.y, p2.z, p2.w};
        float* op = oblk + jj;

        #pragma unroll
        for (int r = 0; r < 8; ++r) {
            const float tn = tnr[r];
            float w0, w1, w2, w3;
            {
                float x = fmaxf(fabsf(tn - tv0), 1.0f);
                float4 te = s_tab[(__float_as_int(x) >> 20) - 1016];
                w0 = (x < te.x) ? te.y : te.z;
            }
            {
                float x = fmaxf(fabsf(tn - tv1), 1.0f);
                float4 te = s_tab[(__float_as_int(x) >> 20) - 1016];
                w1 = (x < te.x) ? te.y : te.z;
            }
            {
                float x = fmaxf(fabsf(tn - tv2), 1.0f);
                float4 te = s_tab[(__float_as_int(x) >> 20) - 1016];
                w2 = (x < te.x) ? te.y : te.z;
            }
            {
                float x = fmaxf(fabsf(tn - tv3), 1.0f);
                float4 te = s_tab[(__float_as_int(x) >> 20) - 1016];
                w3 = (x < te.x) ? te.y : te.z;
            }
            if (full || i0 + r < n) {
                float4 o;
                o.x = w0 + pw[7 - r];
                o.y = w1 + pw[8 - r];
                o.z = w2 + pw[9 - r];
                o.w = w3 + pw[10 - r];
                *reinterpret_cast<float4*>(op) = o;
            }
            op += n;
        }
    }
}

// ---- host-side exact table construction (input-independent) ----

static void build_cell_table_host(CellTab* tab) {
    typedef union { float f; unsigned u; } FU;
    // exact bucket thresholds thr[k], k = 0..80
    float thr[81];
    for (int k = 0; k < 81; ++k) {
        if (k == 0) { thr[0] = 1.0f; continue; }
        volatile float kb = 0.301f;              // force f32 division semantics
        FU l; l.f = (float)(0.301 * (double)k);
        while (!((float)(l.f / kb) >= (float)k)) l.u += 1u;
        for (;;) {
            FU p; p.u = l.u - 1u;
            if ((float)(p.f / kb) >= (float)k) l.u = p.u; else break;
        }
        FU x; x.f = (float)exp((double)l.f);
        while (!((float)log((double)x.f) >= l.f)) x.u += 1u;
        for (;;) {
            FU p; p.u = x.u - 1u;
            if ((float)log((double)p.f) >= l.f) x.u = p.u; else break;
        }
        thr[k] = x.f;
    }
    // k_of(x): largest k with thr[k] <= x
    auto k_of = [&](float x) -> int {
        int k = 0;
        while (k + 1 < 81 && thr[k + 1] <= x) ++k;
        return k;
    };
    for (int c = 0; c < 256; ++c) {
        FU xs; xs.u = (unsigned)(1016 + c) << 20;        // cell start (inclusive)
        FU xe; xe.u = ((unsigned)(1016 + c + 1) << 20) - 1u;  // cell end (inclusive)
        int ks = k_of(xs.f);
        int ke = k_of(xe.f);
        if (ke == ks) {
            tab->thr[c] = 0.0f;                           // never taken
            tab->klo[c] = (unsigned char)ks;
            tab->khi[c] = (unsigned char)ks;
        } else {                                          // exactly one boundary
            tab->thr[c] = thr[ke];
            tab->klo[c] = (unsigned char)ks;
            tab->khi[c] = (unsigned char)ke;
        }
    }
}

extern "C" void kernel_launch(void* const* d_in, const int* in_sizes, int n_in,
                              void* d_out, int out_size) {
    const int*   ts  = (const int*)d_in[0];     // timestamps (B*N) int32
    const float* pos = (const float*)d_in[1];   // pos_biases (2N-1) f32
    const float* tsw = (const float*)d_in[2];   // ts_w (nb+1) f32

    const int n  = (in_sizes[1] + 1) / 2;
    const int B  = in_sizes[0] / n;
    const int nb = in_sizes[2] - 1;

    CellTab tab;
    build_cell_table_host(&tab);

    size_t smem = (size_t)(1024 + n + 16) * sizeof(float);
    dim3 grid((n + 7) / 8, B);
    bias_kernel<<<grid, 256, smem>>>(ts, pos, tsw, (float*)d_out, n, nb, tab);
}